// round 6
// baseline (speedup 1.0000x reference)
#include <cuda_runtime.h>
#include <cuda_bf16.h>
#include <math.h>
#include <stdint.h>

// Shapes
#define HH 16
#define SEQ 2048
#define DD 128
#define MM 4096
#define QQ 4096
#define TQ 128
#define TM 128
#define NTHREADS 256

#define KSEL 20            // approx candidates kept per (row, half)
#define SSTR 132           // sims^T row stride (floats)
#define TILE_B 34816       // 128 rows * 272B (bf16 tile, padded rows)
#define QB_OFF 0
#define KB_OFF(b) (TILE_B + (b) * TILE_B)
#define SIMS_OFF (3 * TILE_B)
#define SMEM_TOTAL (3 * TILE_B + 128 * SSTR * 4)   // 172032

// Scratch: fp32 normalized (for exact rescore) + bf16 (for MMA)
__device__ float          g_qn[HH * QQ * DD];
__device__ float          g_kn[HH * MM * DD];
__device__ __nv_bfloat16  g_qb[HH * QQ * DD];
__device__ __nv_bfloat16  g_kb[HH * MM * DD];

// ---------------- PTX helpers (baseline ISA only: sm_80 features) ----------
__device__ __forceinline__ uint32_t smem_u32(const void* p) {
    uint32_t a;
    asm("{ .reg .u64 t; cvta.to.shared.u64 t, %1; cvt.u32.u64 %0, t; }" : "=r"(a) : "l"(p));
    return a;
}
#define LDSM4(r0, r1, r2, r3, addr) \
    asm volatile("ldmatrix.sync.aligned.m8n8.x4.shared.b16 {%0,%1,%2,%3}, [%4];" \
                 : "=r"(r0), "=r"(r1), "=r"(r2), "=r"(r3) : "r"(addr))
#define MMA16816(c, a0, a1, a2, a3, b0, b1) \
    asm volatile("mma.sync.aligned.m16n8k16.row.col.f32.bf16.bf16.f32 " \
                 "{%0,%1,%2,%3}, {%4,%5,%6,%7}, {%8,%9}, {%0,%1,%2,%3};" \
                 : "+f"((c)[0]), "+f"((c)[1]), "+f"((c)[2]), "+f"((c)[3]) \
                 : "r"(a0), "r"(a1), "r"(a2), "r"(a3), "r"(b0), "r"(b1))
#define CP16(dst, src) \
    asm volatile("cp.async.cg.shared.global [%0], [%1], 16;" :: "r"(dst), "l"(src))
#define CP_COMMIT() asm volatile("cp.async.commit_group;" ::: "memory")
#define CP_WAIT0()  asm volatile("cp.async.wait_group 0;" ::: "memory")

// ---------------- normalization: fp32 + bf16 outputs ----------------
__device__ __forceinline__ void store_both(float* fp, __nv_bfloat16* bp,
                                           size_t off, float4 v, float inv) {
    float x = v.x * inv, y = v.y * inv, z = v.z * inv, w = v.w * inv;
    *(float4*)(fp + off) = make_float4(x, y, z, w);
    __nv_bfloat162* b2 = (__nv_bfloat162*)(bp + off);
    b2[0] = __floats2bfloat162_rn(x, y);
    b2[1] = __floats2bfloat162_rn(z, w);
}

__global__ void norm_k_kernel(const float* __restrict__ km) {
    int wid  = (blockIdx.x * blockDim.x + threadIdx.x) >> 5;
    int lane = threadIdx.x & 31;
    if (wid >= HH * MM) return;
    float4 v = __ldg(((const float4*)(km + (size_t)wid * DD)) + lane);
    float ss = v.x * v.x + v.y * v.y + v.z * v.z + v.w * v.w;
    #pragma unroll
    for (int o = 16; o > 0; o >>= 1) ss += __shfl_xor_sync(0xffffffffu, ss, o);
    float inv = 1.0f / fmaxf(sqrtf(ss), 1e-11f);
    store_both(g_kn, g_kb, (size_t)wid * DD + lane * 4, v, inv);
}

__global__ void norm_q_kernel(const float* __restrict__ query) {
    int wid  = (blockIdx.x * blockDim.x + threadIdx.x) >> 5;
    int lane = threadIdx.x & 31;
    if (wid >= HH * QQ) return;
    int h = wid >> 12;
    int q = wid & (QQ - 1);
    int b = q >> 11;
    int s = q & (SEQ - 1);
    size_t src = ((size_t)((b * HH + h) * SEQ + s)) * DD;
    float4 v = __ldg(((const float4*)(query + src)) + lane);
    float ss = v.x * v.x + v.y * v.y + v.z * v.z + v.w * v.w;
    #pragma unroll
    for (int o = 16; o > 0; o >>= 1) ss += __shfl_xor_sync(0xffffffffu, ss, o);
    float inv = 1.0f / fmaxf(sqrtf(ss), 1e-11f);
    store_both(g_qn, g_qb, (size_t)wid * DD + lane * 4, v, inv);
}

// ---------------- bf16 tile: global (256B rows) -> smem (272B rows), cp.async
__device__ __forceinline__ void cp_tile(uint32_t dst_sb, const __nv_bfloat16* src, int tid) {
    #pragma unroll
    for (int i = 0; i < 8; ++i) {
        int c   = i * 256 + tid;   // 16B chunk 0..2047
        int row = c >> 4;
        int col = c & 15;
        CP16(dst_sb + row * 272 + col * 16,
             (const char*)src + (size_t)row * 256 + col * 16);
    }
}

// Register-resident top-K insert (static indices after unroll)
__device__ __forceinline__ void insertK(float v, int idx, float tv[KSEL], int ti[KSEL],
                                        float& tmin, int& pmin) {
    #pragma unroll
    for (int j = 0; j < KSEL; ++j)
        if (j == pmin) { tv[j] = v; ti[j] = idx; }
    tmin = tv[0]; pmin = 0;
    #pragma unroll
    for (int j = 1; j < KSEL; ++j)
        if (tv[j] < tmin) { tmin = tv[j]; pmin = j; }
}
__device__ __forceinline__ void insert16f(float v, int idx, float tv[16], int ti[16],
                                          float& tmin, int& pmin) {
    #pragma unroll
    for (int j = 0; j < 16; ++j)
        if (j == pmin) { tv[j] = v; ti[j] = idx; }
    tmin = tv[0]; pmin = 0;
    #pragma unroll
    for (int j = 1; j < 16; ++j)
        if (tv[j] < tmin) { tmin = tv[j]; pmin = j; }
}

// ---------------- fused kernel ----------------
__global__ void __launch_bounds__(NTHREADS, 1)
fused_knn_kernel(const float* __restrict__ vmem,
                 const float* __restrict__ outputs,
                 const float* __restrict__ gate,
                 float* __restrict__ out) {
    extern __shared__ char smem[];
    const uint32_t sb = smem_u32(smem);
    const int tid  = threadIdx.x;
    const int w    = tid >> 5;      // warp 0..7
    const int l    = tid & 31;
    const int h     = blockIdx.y;
    const int qbase = blockIdx.x * TQ;

    float* SimsT = (float*)(smem + SIMS_OFF);   // [col][row] stride SSTR

    // ldmatrix per-lane addresses (row-major 8x8 b16 mats; 272B row stride)
    const uint32_t aBase = sb + QB_OFF + (16 * w + (l & 15)) * 272 + ((l & 16) ? 16 : 0);
    const uint32_t bRow  = (l & 15) * 272 + ((l & 16) ? 16 : 0);

    // kick off Q tile + K tile 0
    cp_tile(sb + QB_OFF, &g_qb[((size_t)(h * QQ + qbase)) * DD], tid);
    cp_tile(sb + KB_OFF(0), &g_kb[(size_t)h * MM * DD], tid);
    CP_COMMIT();

    // selection state
    const int srow  = tid & 127;
    const int shalf = tid >> 7;
    float tv[KSEL]; int ti[KSEL];
    #pragma unroll
    for (int j = 0; j < KSEL; ++j) { tv[j] = -1e30f; ti[j] = 0; }
    float tmin = -1e30f; int pmin = 0;

    const int g  = l >> 2;
    const int t2 = (l & 3) * 2;
    const int arow = 16 * w + g;

    for (int t = 0; t < 32; ++t) {
        CP_WAIT0();
        __syncthreads();            // tile t ready; prev SimsT fully consumed

        if (t + 1 < 32) {
            cp_tile(sb + KB_OFF((t + 1) & 1),
                    &g_kb[((size_t)h * MM + (t + 1) * TM) * DD], tid);
            CP_COMMIT();
        }

        const uint32_t kbuf = sb + KB_OFF(t & 1);
        float acc[16][4];
        #pragma unroll
        for (int i = 0; i < 16; ++i)
            #pragma unroll
            for (int j = 0; j < 4; ++j) acc[i][j] = 0.0f;

        #pragma unroll
        for (int ks = 0; ks < 8; ++ks) {
            uint32_t a0, a1, a2, a3;
            LDSM4(a0, a1, a2, a3, aBase + ks * 32);
            #pragma unroll
            for (int nb2 = 0; nb2 < 8; ++nb2) {
                uint32_t r0, r1, r2, r3;
                LDSM4(r0, r1, r2, r3, kbuf + nb2 * 16 * 272 + bRow + ks * 32);
                MMA16816(acc[2 * nb2 + 0], a0, a1, a2, a3, r0, r2);
                MMA16816(acc[2 * nb2 + 1], a0, a1, a2, a3, r1, r3);
            }
        }

        // stage sims TRANSPOSED: SimsT[col][row]  (conflict-free STS.32)
        #pragma unroll
        for (int i = 0; i < 16; ++i) {
            int col = i * 8 + t2;
            SimsT[(col + 0) * SSTR + arow    ] = acc[i][0];
            SimsT[(col + 1) * SSTR + arow    ] = acc[i][1];
            SimsT[(col + 0) * SSTR + arow + 8] = acc[i][2];
            SimsT[(col + 1) * SSTR + arow + 8] = acc[i][3];
        }
        __syncthreads();

        // selection: thread (srow, shalf) scans 64 cols (coalesced LDS.32)
        const int mtb = t * TM + shalf * 64;
        #pragma unroll 8
        for (int cc = 0; cc < 64; ++cc) {
            float v = SimsT[(shalf * 64 + cc) * SSTR + srow];
            if (v > tmin) insertK(v, mtb + cc, tv, ti, tmin, pmin);
        }
    }

    // ---- exact fp32 rescore of this thread's 20 candidates ----
    const float4* qp = (const float4*)(g_qn + ((size_t)(h * QQ + qbase + srow)) * DD);
    #pragma unroll
    for (int j = 0; j < KSEL; ++j) {
        const float4* kp = (const float4*)(g_kn + ((size_t)h * MM + ti[j]) * DD);
        float s0 = 0.f, s1 = 0.f, s2 = 0.f, s3 = 0.f;
        #pragma unroll 8
        for (int u = 0; u < 32; ++u) {
            float4 q = __ldg(qp + u);
            float4 k = __ldg(kp + u);
            s0 = fmaf(q.x, k.x, s0);
            s1 = fmaf(q.y, k.y, s1);
            s2 = fmaf(q.z, k.z, s2);
            s3 = fmaf(q.w, k.w, s3);
        }
        tv[j] = (s0 + s1) + (s2 + s3);   // exact score replaces approx
    }

    // exact top-16 of this thread's 20
    float fv[16]; int fi[16];
    #pragma unroll
    for (int j = 0; j < 16; ++j) { fv[j] = -1e30f; fi[j] = 0; }
    float fmin = -1e30f; int fpm = 0;
    #pragma unroll
    for (int j = 0; j < KSEL; ++j)
        if (tv[j] > fmin) insert16f(tv[j], ti[j], fv, fi, fmin, fpm);

    // ---- merge two half-top-16s per row (reuse Q tile smem) ----
    __syncthreads();
    float* MV = (float*)(smem);                 // 128*32 floats
    int*   MI = (int*)(smem + 16384);           // 128*32 ints
    {
        int mb = srow * 32 + shalf * 16;
        #pragma unroll
        for (int j = 0; j < 16; ++j) { MV[mb + j] = fv[j]; MI[mb + j] = fi[j]; }
    }
    __syncthreads();

    float* FV = (float*)(smem + TILE_B);        // 128*16 floats (in KB0)
    int*   FI = (int*)(smem + TILE_B + 8192);   // 128*16 ints
    if (tid < 128) {
        #pragma unroll
        for (int j = 0; j < 16; ++j) { fv[j] = -1e30f; fi[j] = 0; }
        fmin = -1e30f; fpm = 0;
        #pragma unroll 2
        for (int c = 0; c < 32; ++c) {
            float v = MV[tid * 32 + c];
            if (v > fmin) insert16f(v, MI[tid * 32 + c], fv, fi, fmin, fpm);
        }
        #pragma unroll
        for (int j = 0; j < 16; ++j) { FV[tid * 16 + j] = fv[j]; FI[tid * 16 + j] = fi[j]; }
    }
    __syncthreads();

    // ---- weighted value gather + gated blend ----
    const int row = tid >> 1;
    const int dh  = (tid & 1) << 6;
    float accd[64];
    #pragma unroll
    for (int u = 0; u < 64; ++u) accd[u] = 0.0f;

    const float* vh = vmem + (size_t)h * MM * DD;
    for (int j = 0; j < 16; ++j) {
        float sc = FV[row * 16 + j];
        int   ix = FI[row * 16 + j];
        const float4* vp = (const float4*)(vh + (size_t)ix * DD + dh);
        #pragma unroll
        for (int u = 0; u < 16; ++u) {
            float4 x = __ldg(vp + u);
            accd[4 * u + 0] += sc * x.x;
            accd[4 * u + 1] += sc * x.y;
            accd[4 * u + 2] += sc * x.z;
            accd[4 * u + 3] += sc * x.w;
        }
    }

    size_t li = ((size_t)(h * QQ + qbase + row)) * DD + dh;
    int hout = (int)((li >> 18) & (HH - 1));
    float gg = 1.0f / (1.0f + expf(-__ldg(gate + hout)));
    float og = 1.0f - gg;

    const float4* op = (const float4*)(outputs + li);
    float4*       wp = (float4*)(out + li);
    #pragma unroll
    for (int u = 0; u < 16; ++u) {
        float4 o = __ldg(op + u);
        float4 r;
        r.x = gg * accd[4 * u + 0] + og * o.x;
        r.y = gg * accd[4 * u + 1] + og * o.y;
        r.z = gg * accd[4 * u + 2] + og * o.z;
        r.w = gg * accd[4 * u + 3] + og * o.w;
        wp[u] = r;
    }
}

// ---------------------------------------------------------------------------
extern "C" void kernel_launch(void* const* d_in, const int* in_sizes, int n_in,
                              void* d_out, int out_size) {
    // metadata order: inputs, query, key, value, outputs, gate, key_memories, value_memories
    const float* query   = (const float*)d_in[1];
    const float* outputs = (const float*)d_in[4];
    const float* gate    = (const float*)d_in[5];
    const float* kmem    = (const float*)d_in[6];
    const float* vmem    = (const float*)d_in[7];
    float* out = (float*)d_out;

    cudaFuncSetAttribute(fused_knn_kernel,
                         cudaFuncAttributeMaxDynamicSharedMemorySize, SMEM_TOTAL);

    norm_k_kernel<<<(HH * MM) / 8, 256>>>(kmem);
    norm_q_kernel<<<(HH * QQ) / 8, 256>>>(query);

    dim3 grid(QQ / TQ, HH);  // (32, 16)
    fused_knn_kernel<<<grid, NTHREADS, SMEM_TOTAL>>>(vmem, outputs, gate, out);
}

// round 7
// speedup vs baseline: 1.6210x; 1.6210x over previous
#include <cuda_runtime.h>
#include <math.h>

// Shapes (hardcoded for this problem instance)
#define BB   2
#define HH   16
#define SS   2048
#define DD   128
#define MM   4096          // memories per head
#define QQ   4096          // B*S queries per head

#define TQ   128           // query tile per CTA
#define TM   128           // memory tile per iteration
#define NTHREADS 256
#define SSTRIDE 132        // sims row stride: divisible by 4 (float4-aligned rows)

// Scratch: normalized queries and keys (32 MB each)
__device__ float g_qn[HH * QQ * DD];
__device__ float g_kn[HH * MM * DD];

// ---------------------------------------------------------------------------
// Normalization kernels: one warp per 128-float row
// ---------------------------------------------------------------------------
__global__ void norm_k_kernel(const float* __restrict__ km) {
    int wid  = (blockIdx.x * blockDim.x + threadIdx.x) >> 5;
    int lane = threadIdx.x & 31;
    if (wid >= HH * MM) return;
    float4 v = __ldg(((const float4*)(km + (size_t)wid * DD)) + lane);
    float ss = v.x * v.x + v.y * v.y + v.z * v.z + v.w * v.w;
    #pragma unroll
    for (int o = 16; o > 0; o >>= 1) ss += __shfl_xor_sync(0xffffffffu, ss, o);
    float inv = 1.0f / fmaxf(sqrtf(ss), 1e-11f);
    float4 r = make_float4(v.x * inv, v.y * inv, v.z * inv, v.w * inv);
    ((float4*)(g_kn + (size_t)wid * DD))[lane] = r;
}

__global__ void norm_q_kernel(const float* __restrict__ query) {
    int wid  = (blockIdx.x * blockDim.x + threadIdx.x) >> 5;
    int lane = threadIdx.x & 31;
    if (wid >= HH * QQ) return;
    int h = wid >> 12;          // / 4096
    int q = wid & (QQ - 1);
    int b = q >> 11;            // / 2048
    int s = q & (SS - 1);
    size_t src = ((size_t)((b * HH + h) * SS + s)) * DD;
    float4 v = __ldg(((const float4*)(query + src)) + lane);
    float ss = v.x * v.x + v.y * v.y + v.z * v.z + v.w * v.w;
    #pragma unroll
    for (int o = 16; o > 0; o >>= 1) ss += __shfl_xor_sync(0xffffffffu, ss, o);
    float inv = 1.0f / fmaxf(sqrtf(ss), 1e-11f);
    float4 r = make_float4(v.x * inv, v.y * inv, v.z * inv, v.w * inv);
    ((float4*)(g_qn + (size_t)wid * DD))[lane] = r;
}

// ---------------------------------------------------------------------------
// Load a 128x128 fp32 tile (row-major [row][d]) into SMEM transposed [d][row]
// with XOR group-swizzle: element (row, d) -> dst[d*128 + ((row>>2)^((d>>2)&7))*4 + (row&3)]
//
// Lane mapping chosen so a warp covers 8 rows (stride 4) x 4 d-chunks per
// iteration: STS conflicts drop from 32-way (row-major traversal) to ~4-way.
//   warp w owns d-chunks [w*16 .. w*16+15]; lane l: dbase = w*16 + (l>>3)*4
//   iter i: row = (i>>2)*32 + (l&7)*4 + (i&3)
// ---------------------------------------------------------------------------
__device__ __forceinline__ void load_tile_T(const float* __restrict__ src,
                                            float* __restrict__ dst, int tid) {
    const int w = tid >> 5;
    const int l = tid & 31;
    const int dbase = (w << 4) + ((l >> 3) << 2);   // 0..124, step 4
    #pragma unroll
    for (int i = 0; i < 16; ++i) {
        const int rl  = i & 3;
        const int row = ((i >> 2) << 5) + ((l & 7) << 2) + rl;
        float4 v = __ldg((const float4*)(src + (size_t)row * DD + dbase));
        float vv[4] = {v.x, v.y, v.z, v.w};
        const int cg = row >> 2;
        #pragma unroll
        for (int j = 0; j < 4; ++j) {
            const int d = dbase + j;
            dst[d * 128 + ((cg ^ ((d >> 2) & 7)) << 2) + rl] = vv[j];
        }
    }
}

// Register-resident top-16 insert (static indices after unroll -> no spill)
__device__ __forceinline__ void insert16(float v, int idx,
                                         float tv[16], int ti[16],
                                         float& tmin, int& pmin) {
    #pragma unroll
    for (int j = 0; j < 16; ++j) {
        if (j == pmin) { tv[j] = v; ti[j] = idx; }
    }
    tmin = tv[0]; pmin = 0;
    #pragma unroll
    for (int j = 1; j < 16; ++j) {
        if (tv[j] < tmin) { tmin = tv[j]; pmin = j; }
    }
}

// ---------------------------------------------------------------------------
// Fused kernel: per (head, 128-query tile):
//   loop over M in 128-chunks: SGEMM 128x128x128 -> SMEM sims -> top-16
//   then merge halves, gather values, weighted sum, gated blend, write output
//
// Column ownership (per thread): pairs {tx*2 + 32*j, tx*2 + 32*j + 1}, j=0..3
//  -> B operand pairs are conflict-free LDS.64 from the swizzled K tile
//  -> sims staging is STS.64 with <=2-way conflicts
// ---------------------------------------------------------------------------
__global__ void __launch_bounds__(NTHREADS, 1)
fused_knn_kernel(const float* __restrict__ vmem,
                 const float* __restrict__ outputs,
                 const float* __restrict__ gate,
                 float* __restrict__ out) {
    extern __shared__ float sm[];
    float* Qs = sm;                 // 16384 floats: Q tile [d][q] swizzled
    float* Ks = sm + 16384;         // 16384 floats: K tile [d][m] swizzled
    float* Ss = sm + 32768;         // 128*SSTRIDE floats: sims [q][m]

    const int h     = blockIdx.y;
    const int qbase = blockIdx.x * TQ;
    const int tid   = threadIdx.x;
    const int ty    = tid >> 4;     // 0..15 (query sub-rows: rows ty*8..ty*8+7)
    const int tx    = tid & 15;     // 0..15 (column-pair id)
    const int txg   = tx >> 1;      // 0..7  (column 4-group base)
    const int txo   = (tx & 1) << 1;// 0 or 2 (offset within 4-group)
    const int srow  = tid & 127;    // selection row
    const int shalf = tid >> 7;     // selection half (0/1)

    // Load and keep the Q tile resident
    load_tile_T(g_qn + ((size_t)(h * QQ + qbase)) * DD, Qs, tid);

    // top-16 state (registers)
    float tv[16]; int ti[16];
    #pragma unroll
    for (int j = 0; j < 16; ++j) { tv[j] = -1e30f; ti[j] = 0; }
    float tmin = -1e30f; int pmin = 0;

    const float* kh = g_kn + (size_t)h * MM * DD;

    for (int mt = 0; mt < MM; mt += TM) {
        __syncthreads();  // prev selection done with Ss; prev GEMM done with Ks
        load_tile_T(kh + (size_t)mt * DD, Ks, tid);
        __syncthreads();

        float acc[8][8];
        #pragma unroll
        for (int i = 0; i < 8; ++i)
            #pragma unroll
            for (int j = 0; j < 8; ++j) acc[i][j] = 0.0f;

        #pragma unroll 4
        for (int kk = 0; kk < 128; ++kk) {
            const int s = (kk >> 2) & 7;
            const float* qrow = Qs + kk * 128;
            const float* krow = Ks + kk * 128;
            // A: 8 query rows (two swizzled float4 groups)
            const float4 a0 = *(const float4*)&qrow[(((ty * 2)     ^ s) << 2)];
            const float4 a1 = *(const float4*)&qrow[(((ty * 2 + 1) ^ s) << 2)];
            // B: 4 column-pairs at m = tx*2 + 32j (conflict-free LDS.64)
            float2 b[4];
            #pragma unroll
            for (int j = 0; j < 4; ++j)
                b[j] = *(const float2*)&krow[(((txg ^ s) + 8 * j) << 2) + txo];
            const float av[8] = {a0.x, a0.y, a0.z, a0.w, a1.x, a1.y, a1.z, a1.w};
            #pragma unroll
            for (int i = 0; i < 8; ++i) {
                #pragma unroll
                for (int j = 0; j < 4; ++j) {
                    acc[i][2 * j + 0] = fmaf(av[i], b[j].x, acc[i][2 * j + 0]);
                    acc[i][2 * j + 1] = fmaf(av[i], b[j].y, acc[i][2 * j + 1]);
                }
            }
        }

        // stage sims: row = ty*8+i, col-pair at tx*2 + 32j (STS.64, ~2-way)
        #pragma unroll
        for (int i = 0; i < 8; ++i) {
            float* srowp = Ss + (ty * 8 + i) * SSTRIDE + tx * 2;
            #pragma unroll
            for (int j = 0; j < 4; ++j)
                *(float2*)&srowp[32 * j] = make_float2(acc[i][2 * j], acc[i][2 * j + 1]);
        }
        __syncthreads();

        // selection: thread (srow, shalf) scans 64 candidates (float4, aligned)
        const float4* sp = (const float4*)(Ss + srow * SSTRIDE + shalf * 64);
        const int base = mt + shalf * 64;
        #pragma unroll 4
        for (int c4 = 0; c4 < 16; ++c4) {
            float4 v = sp[c4];
            int bi = base + c4 * 4;
            if (v.x > tmin) insert16(v.x, bi + 0, tv, ti, tmin, pmin);
            if (v.y > tmin) insert16(v.y, bi + 1, tv, ti, tmin, pmin);
            if (v.z > tmin) insert16(v.z, bi + 2, tv, ti, tmin, pmin);
            if (v.w > tmin) insert16(v.w, bi + 3, tv, ti, tmin, pmin);
        }
    }

    // ---- merge the two halves per row ----
    __syncthreads();
    float* MV = Ks;                       // 128*32 floats
    int*   MI = (int*)(Ks + 4096);        // 128*32 ints
    {
        int mb = srow * 32 + shalf * 16;
        #pragma unroll
        for (int j = 0; j < 16; ++j) { MV[mb + j] = tv[j]; MI[mb + j] = ti[j]; }
    }
    __syncthreads();

    float* FV = Qs;                       // 128*16 floats
    int*   FI = (int*)(Qs + 2048);        // 128*16 ints
    if (tid < 128) {
        #pragma unroll
        for (int j = 0; j < 16; ++j) { tv[j] = -1e30f; ti[j] = 0; }
        tmin = -1e30f; pmin = 0;
        #pragma unroll 2
        for (int c = 0; c < 32; ++c) {
            float v = MV[tid * 32 + c];
            if (v > tmin) insert16(v, MI[tid * 32 + c], tv, ti, tmin, pmin);
        }
        #pragma unroll
        for (int j = 0; j < 16; ++j) { FV[tid * 16 + j] = tv[j]; FI[tid * 16 + j] = ti[j]; }
    }
    __syncthreads();

    // ---- weighted value gather + gated blend ----
    const int row = tid >> 1;             // 0..127
    const int dh  = (tid & 1) << 6;       // 0 or 64
    float accd[64];
    #pragma unroll
    for (int t = 0; t < 64; ++t) accd[t] = 0.0f;

    const float* vh = vmem + (size_t)h * MM * DD;
    for (int j = 0; j < 16; ++j) {
        float sc = FV[row * 16 + j];
        int   ix = FI[row * 16 + j];
        const float4* vp = (const float4*)(vh + (size_t)ix * DD + dh);
        #pragma unroll
        for (int t = 0; t < 16; ++t) {
            float4 w = __ldg(vp + t);
            accd[4 * t + 0] += sc * w.x;
            accd[4 * t + 1] += sc * w.y;
            accd[4 * t + 2] += sc * w.z;
            accd[4 * t + 3] += sc * w.w;
        }
    }

    // Output flat index == wm flat index (raw reshape); gate head from out layout
    size_t l = ((size_t)(h * QQ + qbase + row)) * DD + dh;
    int hout = (int)((l >> 18) & (HH - 1));     // S*D = 2^18
    float gg = 1.0f / (1.0f + expf(-__ldg(gate + hout)));
    float og = 1.0f - gg;

    const float4* op = (const float4*)(outputs + l);
    float4*       wp = (float4*)(out + l);
    #pragma unroll
    for (int t = 0; t < 16; ++t) {
        float4 o = __ldg(op + t);
        float4 r;
        r.x = gg * accd[4 * t + 0] + og * o.x;
        r.y = gg * accd[4 * t + 1] + og * o.y;
        r.z = gg * accd[4 * t + 2] + og * o.z;
        r.w = gg * accd[4 * t + 3] + og * o.w;
        wp[t] = r;
    }
}

// ---------------------------------------------------------------------------
extern "C" void kernel_launch(void* const* d_in, const int* in_sizes, int n_in,
                              void* d_out, int out_size) {
    // metadata order: inputs, query, key, value, outputs, gate, key_memories, value_memories
    const float* query   = (const float*)d_in[1];
    const float* outputs = (const float*)d_in[4];
    const float* gate    = (const float*)d_in[5];
    const float* kmem    = (const float*)d_in[6];
    const float* vmem    = (const float*)d_in[7];
    float* out = (float*)d_out;

    const int smem_bytes = (32768 + 128 * SSTRIDE) * (int)sizeof(float);  // 198656
    cudaFuncSetAttribute(fused_knn_kernel,
                         cudaFuncAttributeMaxDynamicSharedMemorySize, smem_bytes);

    norm_k_kernel<<<(HH * MM) / 8, 256>>>(kmem);
    norm_q_kernel<<<(HH * QQ) / 8, 256>>>(query);

    dim3 grid(QQ / TQ, HH);  // (32, 16)
    fused_knn_kernel<<<grid, NTHREADS, smem_bytes>>>(vmem, outputs, gate, out);
}

// round 8
// speedup vs baseline: 2.2354x; 1.3790x over previous
#include <cuda_runtime.h>
#include <math.h>

// Shapes (hardcoded for this problem instance)
#define BB   2
#define HH   16
#define SS   2048
#define DD   128
#define MM   4096          // memories per head
#define QQ   4096          // B*S queries per head

#define TQ   128           // query tile per CTA
#define TM   128           // memory tile per iteration
#define NTHREADS 256

// Scratch: normalized queries and keys (32 MB each)
__device__ float g_qn[HH * QQ * DD];
__device__ float g_kn[HH * MM * DD];

// ---------------------------------------------------------------------------
// Normalization kernels: one warp per 128-float row
// ---------------------------------------------------------------------------
__global__ void norm_k_kernel(const float* __restrict__ km) {
    int wid  = (blockIdx.x * blockDim.x + threadIdx.x) >> 5;
    int lane = threadIdx.x & 31;
    if (wid >= HH * MM) return;
    float4 v = __ldg(((const float4*)(km + (size_t)wid * DD)) + lane);
    float ss = v.x * v.x + v.y * v.y + v.z * v.z + v.w * v.w;
    #pragma unroll
    for (int o = 16; o > 0; o >>= 1) ss += __shfl_xor_sync(0xffffffffu, ss, o);
    float inv = 1.0f / fmaxf(sqrtf(ss), 1e-11f);
    float4 r = make_float4(v.x * inv, v.y * inv, v.z * inv, v.w * inv);
    ((float4*)(g_kn + (size_t)wid * DD))[lane] = r;
}

__global__ void norm_q_kernel(const float* __restrict__ query) {
    int wid  = (blockIdx.x * blockDim.x + threadIdx.x) >> 5;
    int lane = threadIdx.x & 31;
    if (wid >= HH * QQ) return;
    int h = wid >> 12;          // / 4096
    int q = wid & (QQ - 1);
    int b = q >> 11;            // / 2048
    int s = q & (SS - 1);
    size_t src = ((size_t)((b * HH + h) * SS + s)) * DD;
    float4 v = __ldg(((const float4*)(query + src)) + lane);
    float ss = v.x * v.x + v.y * v.y + v.z * v.z + v.w * v.w;
    #pragma unroll
    for (int o = 16; o > 0; o >>= 1) ss += __shfl_xor_sync(0xffffffffu, ss, o);
    float inv = 1.0f / fmaxf(sqrtf(ss), 1e-11f);
    float4 r = make_float4(v.x * inv, v.y * inv, v.z * inv, v.w * inv);
    ((float4*)(g_qn + (size_t)wid * DD))[lane] = r;
}

// ---------------------------------------------------------------------------
// Load a 128x128 fp32 tile (row-major [row][d]) into SMEM transposed [d][row]
// with XOR group-swizzle: element (row, d) -> dst[d*128 + ((row>>2)^((d>>2)&7))*4 + (row&3)]
//
// Conflict-aware traversal: warp w owns d-chunks [w*16 .. w*16+15];
// lane l: dbase = w*16 + (l>>3)*4; iter i: row = (i>>2)*32 + (l&7)*4 + (i&3).
// STS conflicts drop from 32-way (row-major traversal) to ~4-way.
// The resulting SMEM layout is IDENTICAL to the round-1 kernel's.
// ---------------------------------------------------------------------------
__device__ __forceinline__ void load_tile_T(const float* __restrict__ src,
                                            float* __restrict__ dst, int tid) {
    const int w = tid >> 5;
    const int l = tid & 31;
    const int dbase = (w << 4) + ((l >> 3) << 2);   // 0..124, step 4
    #pragma unroll
    for (int i = 0; i < 16; ++i) {
        const int rl  = i & 3;
        const int row = ((i >> 2) << 5) + ((l & 7) << 2) + rl;
        float4 v = __ldg((const float4*)(src + (size_t)row * DD + dbase));
        float vv[4] = {v.x, v.y, v.z, v.w};
        const int cg = row >> 2;
        #pragma unroll
        for (int j = 0; j < 4; ++j) {
            const int d = dbase + j;
            dst[d * 128 + ((cg ^ ((d >> 2) & 7)) << 2) + rl] = vv[j];
        }
    }
}

// Register-resident top-16 insert (static indices after unroll -> no spill)
__device__ __forceinline__ void insert16(float v, int idx,
                                         float tv[16], int ti[16],
                                         float& tmin, int& pmin) {
    #pragma unroll
    for (int j = 0; j < 16; ++j) {
        if (j == pmin) { tv[j] = v; ti[j] = idx; }
    }
    tmin = tv[0]; pmin = 0;
    #pragma unroll
    for (int j = 1; j < 16; ++j) {
        if (tv[j] < tmin) { tmin = tv[j]; pmin = j; }
    }
}

// ---------------------------------------------------------------------------
// Fused kernel (round-1 structure): per (head, 128-query tile):
//   loop over M in 128-chunks: SGEMM 128x128x128 -> SMEM sims -> top-16 update
//   then merge halves, gather values, weighted sum, gated blend, write output
// ---------------------------------------------------------------------------
__global__ void __launch_bounds__(NTHREADS, 1)
fused_knn_kernel(const float* __restrict__ vmem,
                 const float* __restrict__ outputs,
                 const float* __restrict__ gate,
                 float* __restrict__ out) {
    extern __shared__ float sm[];
    float* Qs = sm;                 // 16384 floats: Q tile [d][q] swizzled
    float* Ks = sm + 16384;         // 16384 floats: K tile [d][m] swizzled
    float* Ss = sm + 32768;         // 128*129 floats: sims [q][m] padded

    const int h     = blockIdx.y;
    const int qbase = blockIdx.x * TQ;
    const int tid   = threadIdx.x;
    const int ty    = tid >> 4;     // 0..15 (query sub-rows)
    const int tx    = tid & 15;     // 0..15 (memory sub-cols)
    const int srow  = tid & 127;    // selection row
    const int shalf = tid >> 7;     // selection half (0/1)

    // Load and keep the Q tile resident
    load_tile_T(g_qn + ((size_t)(h * QQ + qbase)) * DD, Qs, tid);

    // top-16 state (registers)
    float tv[16]; int ti[16];
    #pragma unroll
    for (int j = 0; j < 16; ++j) { tv[j] = -1e30f; ti[j] = 0; }
    float tmin = -1e30f; int pmin = 0;

    const float* kh = g_kn + (size_t)h * MM * DD;

    for (int mt = 0; mt < MM; mt += TM) {
        __syncthreads();  // prev selection done with Ss; prev GEMM done with Ks; Qs ready (1st)
        load_tile_T(kh + (size_t)mt * DD, Ks, tid);
        __syncthreads();

        float acc[8][8];
        #pragma unroll
        for (int i = 0; i < 8; ++i)
            #pragma unroll
            for (int j = 0; j < 8; ++j) acc[i][j] = 0.0f;

        #pragma unroll 4
        for (int kk = 0; kk < 128; ++kk) {
            int s = (kk >> 2) & 7;
            const float4 a0 = *(const float4*)&Qs[kk * 128 + (((ty * 2)     ^ s) << 2)];
            const float4 a1 = *(const float4*)&Qs[kk * 128 + (((ty * 2 + 1) ^ s) << 2)];
            const float4 b0 = *(const float4*)&Ks[kk * 128 + (((tx * 2)     ^ s) << 2)];
            const float4 b1 = *(const float4*)&Ks[kk * 128 + (((tx * 2 + 1) ^ s) << 2)];
            float a[8] = {a0.x, a0.y, a0.z, a0.w, a1.x, a1.y, a1.z, a1.w};
            float b[8] = {b0.x, b0.y, b0.z, b0.w, b1.x, b1.y, b1.z, b1.w};
            #pragma unroll
            for (int i = 0; i < 8; ++i)
                #pragma unroll
                for (int j = 0; j < 8; ++j) acc[i][j] += a[i] * b[j];
        }

        // stage sims to shared (padded stride 129 -> conflict-free column scans)
        #pragma unroll
        for (int i = 0; i < 8; ++i)
            #pragma unroll
            for (int j = 0; j < 8; ++j)
                Ss[(ty * 8 + i) * 129 + tx * 8 + j] = acc[i][j];
        __syncthreads();

        // selection: thread (srow, shalf) scans 64 candidates
        const float* sp = Ss + srow * 129 + shalf * 64;
        const int base = mt + shalf * 64;
        #pragma unroll 4
        for (int c = 0; c < 64; ++c) {
            float v = sp[c];
            if (v > tmin) insert16(v, base + c, tv, ti, tmin, pmin);
        }
    }

    // ---- merge the two halves per row ----
    __syncthreads();
    float* MV = Ks;                       // 128*32 floats
    int*   MI = (int*)(Ks + 4096);        // 128*32 ints
    {
        int mb = srow * 32 + shalf * 16;
        #pragma unroll
        for (int j = 0; j < 16; ++j) { MV[mb + j] = tv[j]; MI[mb + j] = ti[j]; }
    }
    __syncthreads();

    float* FV = Qs;                       // 128*16 floats
    int*   FI = (int*)(Qs + 2048);        // 128*16 ints
    if (tid < 128) {
        #pragma unroll
        for (int j = 0; j < 16; ++j) { tv[j] = -1e30f; ti[j] = 0; }
        tmin = -1e30f; pmin = 0;
        #pragma unroll 2
        for (int c = 0; c < 32; ++c) {
            float v = MV[tid * 32 + c];
            if (v > tmin) insert16(v, MI[tid * 32 + c], tv, ti, tmin, pmin);
        }
        #pragma unroll
        for (int j = 0; j < 16; ++j) { FV[tid * 16 + j] = tv[j]; FI[tid * 16 + j] = ti[j]; }
    }
    __syncthreads();

    // ---- weighted value gather + gated blend ----
    const int row = tid >> 1;             // 0..127
    const int dh  = (tid & 1) << 6;       // 0 or 64
    float accd[64];
    #pragma unroll
    for (int t = 0; t < 64; ++t) accd[t] = 0.0f;

    const float* vh = vmem + (size_t)h * MM * DD;
    for (int j = 0; j < 16; ++j) {
        float sc = FV[row * 16 + j];
        int   ix = FI[row * 16 + j];
        const float4* vp = (const float4*)(vh + (size_t)ix * DD + dh);
        #pragma unroll
        for (int t = 0; t < 16; ++t) {
            float4 w = __ldg(vp + t);
            accd[4 * t + 0] += sc * w.x;
            accd[4 * t + 1] += sc * w.y;
            accd[4 * t + 2] += sc * w.z;
            accd[4 * t + 3] += sc * w.w;
        }
    }

    // Output flat index == wm flat index (raw reshape); gate head from out layout
    size_t l = ((size_t)(h * QQ + qbase + row)) * DD + dh;
    int hout = (int)((l >> 18) & (HH - 1));     // S*D = 2^18
    float gg = 1.0f / (1.0f + expf(-__ldg(gate + hout)));
    float og = 1.0f - gg;

    const float4* op = (const float4*)(outputs + l);
    float4*       wp = (float4*)(out + l);
    #pragma unroll
    for (int t = 0; t < 16; ++t) {
        float4 o = __ldg(op + t);
        float4 r;
        r.x = gg * accd[4 * t + 0] + og * o.x;
        r.y = gg * accd[4 * t + 1] + og * o.y;
        r.z = gg * accd[4 * t + 2] + og * o.z;
        r.w = gg * accd[4 * t + 3] + og * o.w;
        wp[t] = r;
    }
}

// ---------------------------------------------------------------------------
extern "C" void kernel_launch(void* const* d_in, const int* in_sizes, int n_in,
                              void* d_out, int out_size) {
    // metadata order: inputs, query, key, value, outputs, gate, key_memories, value_memories
    const float* query   = (const float*)d_in[1];
    const float* outputs = (const float*)d_in[4];
    const float* gate    = (const float*)d_in[5];
    const float* kmem    = (const float*)d_in[6];
    const float* vmem    = (const float*)d_in[7];
    float* out = (float*)d_out;

    const int smem_bytes = (32768 + 128 * 129) * (int)sizeof(float);  // 197120
    cudaFuncSetAttribute(fused_knn_kernel,
                         cudaFuncAttributeMaxDynamicSharedMemorySize, smem_bytes);

    norm_k_kernel<<<(HH * MM) / 8, 256>>>(kmem);
    norm_q_kernel<<<(HH * QQ) / 8, 256>>>(query);

    dim3 grid(QQ / TQ, HH);  // (32, 16)
    fused_knn_kernel<<<grid, NTHREADS, smem_bytes>>>(vmem, outputs, gate, out);
}